// round 15
// baseline (speedup 1.0000x reference)
#include <cuda_runtime.h>
#include <cuda_bf16.h>

#define T_ 128
#define B_ 512
#define D_ 500
#define D4_ 125   // D/4 float4 per row
#define PF 8      // prefetch depth (rows ahead)

// Scratch (no allocation allowed).
__device__ int g_newlen[B_];
__device__ unsigned int g_arrive;   // zero-init; monotonic across graph replays

// ---------------------------------------------------------------------------
// Single fused kernel. One block per SOURCE column b, 128 threads.
//
// Prologue ordering is the point of this round: the barrier-critical
// dependent chain (src -> token_lengths gather) runs to COMPLETION before
// the PF=8 embedding prefetch burst is issued, so the gather's memory
// requests never queue behind 8.4MB of prefetch traffic (the R8-R11 flaw).
// The prefetches then drain during the scan + barrier spin.
//
//   1. src load + token_lengths gather (parallel, 2 dependent round trips)
//   2. s_len to smem, __syncthreads
//   3. ALL threads issue PF=8 embv prefetches (fills DRAM during 4-6)
//   4. lane 0: compact greedy scan (smem-only), publish g_newlen[b]
//   5. grid barrier: monotonic counter arrive + plain-load spin
//      (all 512 blocks co-resident: __launch_bounds__(128,4) -> 592 slots)
//   6. stable descending rank over all newlens
//   7. stream t=0..127 with 8-deep ring: read each input row ONCE,
//      accumulate valid rows, write-through rows t>=L, flush accumulator
//      at segment-end flags.  Traffic: 262 MB total.
// ---------------------------------------------------------------------------
__global__ __launch_bounds__(T_, 4) void fused_kernel(
    const float4* __restrict__ embv,
    const int*    __restrict__ src,
    const int*    __restrict__ token_lengths,
    const int*    __restrict__ token_len_p,
    float4*       __restrict__ outv,
    float*        __restrict__ out_len,
    int write_len)
{
    __shared__ unsigned char  s_len[T_];
    __shared__ unsigned short s_meta[T_];   // bit0=valid, bits[1:]=emit seg+1
    __shared__ int s_warp[4];
    __shared__ int s_rank;

    int b = blockIdx.x;
    int i = threadIdx.x;

    const long stride = (long)B_ * D4_;     // float4s per t-slab
    bool active = (i < D4_);
    int  ic     = active ? i : (D4_ - 1);   // clamped: loads always valid
    long ibase  = (long)b * D4_ + ic;

    // ---- 1-2: barrier-critical chain, run to completion FIRST ----
    int s = __ldcg(&src[i * B_ + b]);
    int l = (s == 1) ? 0 : ((s == 0) ? 4 : token_lengths[s]);
    s_len[i]  = (unsigned char)l;
    s_meta[i] = 0;
    __syncthreads();

    // ---- 3: now issue the prefetch burst (drains during scan + spin) ----
    float4 buf[PF];
    #pragma unroll
    for (int k = 0; k < PF; k++) buf[k] = embv[ibase + (long)k * stride];

    // ---- 4-5: scan + publish + barrier (lane 0) ----
    if (i == 0) {
        int token_len = token_len_p ? token_len_p[0] : 20;

        const uint4* p4 = (const uint4*)s_len;
        int seg = 0, curr = 0, last_t = 0;

        uint4 cur = p4[0];
        for (int k = 0; k < T_ / 16; k++) {      // compact body, L0-resident
            uint4 nxt = (k < T_ / 16 - 1) ? p4[k + 1] : cur;
            uint wa0 = cur.x, wa1 = cur.y, wa2 = cur.z, wa3 = cur.w;
            #pragma unroll
            for (int q = 0; q < 16; q++) {       // compile-time indices only
                uint word = (q < 4) ? wa0 : (q < 8) ? wa1 : (q < 12) ? wa2 : wa3;
                int ll = (word >> ((q & 3) * 8)) & 0xFF;
                int tt = k * 16 + q;
                bool valid = (ll != 0);
                bool close = valid & (curr > 0) & (curr + ll > token_len);
                if (close) s_meta[last_t] |= (unsigned short)((seg + 1) << 1);
                seg  += (int)close;
                curr  = close ? 0 : curr;
                if (valid) s_meta[tt] |= 1;
                curr  += valid ? ll : 0;
                last_t = valid ? tt : last_t;
            }
            cur = nxt;
        }
        bool trail = (curr > 0);
        if (trail) s_meta[last_t] |= (unsigned short)((seg + 1) << 1);
        seg += (int)trail;
        g_newlen[b] = seg;

        // grid barrier: atomic arrive, plain-load spin (replay-safe target)
        __threadfence();
        unsigned int arrived = atomicAdd(&g_arrive, 1u);
        unsigned int target  = (arrived / (unsigned)B_ + 1u) * (unsigned)B_;
        volatile unsigned int* pa = &g_arrive;
        while (*pa < target) __nanosleep(32);
        __threadfence();
    }
    __syncthreads();

    // ---- 6: stable descending rank over all columns ----
    int myl = g_newlen[b];
    const int4* len4 = (const int4*)g_newlen;   // 512/4 = 128 == blockDim
    int4 v4 = __ldcg(&len4[i]);                 // bypass L1: cross-SM data
    int j = 4 * i;
    int cnt = 0;
    cnt += (v4.x > myl) || (v4.x == myl && (j + 0) < b);
    cnt += (v4.y > myl) || (v4.y == myl && (j + 1) < b);
    cnt += (v4.z > myl) || (v4.z == myl && (j + 2) < b);
    cnt += (v4.w > myl) || (v4.w == myl && (j + 3) < b);
    #pragma unroll
    for (int o = 16; o > 0; o >>= 1) cnt += __shfl_down_sync(0xFFFFFFFFu, cnt, o);
    if ((i & 31) == 0) s_warp[i >> 5] = cnt;
    __syncthreads();
    if (i == 0) {
        int rank = s_warp[0] + s_warp[1] + s_warp[2] + s_warp[3];
        s_rank = rank;
        if (write_len) out_len[rank] = (float)myl;
    }
    __syncthreads();

    int  bo    = s_rank;
    int  L     = myl;
    long obase = (long)bo * D4_ + i;

    // ---- 7: streaming loop with 8-deep ring buffer ----
    float4 acc = make_float4(0.f, 0.f, 0.f, 0.f);

    for (int to = 0; to < T_; to += PF) {
        #pragma unroll
        for (int k = 0; k < PF; k++) {
            int t = to + k;
            float4 v = buf[k];
            if (t + PF < T_)                       // refill slot (stays PF ahead)
                buf[k] = embv[ibase + (long)(t + PF) * stride];

            unsigned int m = s_meta[t];
            if (m & 1u) {
                acc.x += v.x; acc.y += v.y; acc.z += v.z; acc.w += v.w;
            }
            if (t >= L && active)
                outv[obase + (long)t * stride] = v;

            unsigned int e = m >> 1;
            if (e && active) {
                outv[obase + (long)((int)e - 1) * stride] = acc;
                acc = make_float4(0.f, 0.f, 0.f, 0.f);
            }
        }
    }
}

// ---------------------------------------------------------------------------
extern "C" void kernel_launch(void* const* d_in, const int* in_sizes, int n_in,
                              void* d_out, int out_size)
{
    const float* emb           = (const float*)d_in[0];   // (T,B,D) fp32
    const int*   src           = (const int*)d_in[1];     // (T,B) int32
    // d_in[2] = lengths (unused by reference computation)
    const int*   token_lengths = (const int*)d_in[3];     // (VOCAB,) int32
    const int*   token_len_p   = (n_in >= 5) ? (const int*)d_in[4] : nullptr;

    float* out = (float*)d_out;
    const long emb_elems = (long)T_ * B_ * D_;
    int write_len = (out_size >= emb_elems + B_) ? 1 : 0;

    fused_kernel<<<B_, T_>>>((const float4*)emb, src, token_lengths, token_len_p,
                             (float4*)out, out + emb_elems, write_len);
}

// round 16
// speedup vs baseline: 1.0119x; 1.0119x over previous
#include <cuda_runtime.h>
#include <cuda_bf16.h>

#define T_ 128
#define B_ 512
#define D_ 500
#define D4_ 125   // D/4 float4 per row
#define PF 8      // prefetch depth (rows ahead)
#define H0 63     // chunks in half 0  (half 1 gets 62)

// Scratch (no allocation allowed): control-plane metadata.
// g_meta[b*T_+t]: bit0 = token t valid; bits[1:15] = (seg_to_emit_after_t + 1), 0 = none.
__device__ unsigned short g_meta[B_ * T_];
__device__ int g_newlen[B_];

// ---------------------------------------------------------------------------
// Kernel 1: per-column greedy packing scan (control plane). R12 body.
// ---------------------------------------------------------------------------
__global__ __launch_bounds__(T_) void setup_kernel(const int* __restrict__ src,
                                                   const int* __restrict__ token_lengths,
                                                   const int* __restrict__ token_len_p)
{
    __shared__ unsigned char  s_len[T_];
    __shared__ unsigned short s_meta[T_];

    int b = blockIdx.x;
    int t = threadIdx.x;

    // Parallel gather phase.
    int s = __ldcg(&src[t * B_ + b]);
    int l = (s == 1) ? 0 : ((s == 0) ? 4 : token_lengths[s]);
    s_len[t]  = (unsigned char)l;
    s_meta[t] = 0;
    __syncthreads();

    if (t == 0) {
        int token_len = token_len_p ? token_len_p[0] : 20;

        const uint4* p4 = (const uint4*)s_len;
        int seg = 0, curr = 0, last_t = 0;

        uint4 cur = p4[0];
        for (int k = 0; k < T_ / 16; k++) {      // compact body, L0-resident
            uint4 nxt = (k < T_ / 16 - 1) ? p4[k + 1] : cur;
            uint wa0 = cur.x, wa1 = cur.y, wa2 = cur.z, wa3 = cur.w;
            #pragma unroll
            for (int q = 0; q < 16; q++) {       // compile-time indices only
                uint word = (q < 4) ? wa0 : (q < 8) ? wa1 : (q < 12) ? wa2 : wa3;
                int ll = (word >> ((q & 3) * 8)) & 0xFF;
                int tt = k * 16 + q;
                bool valid = (ll != 0);
                bool close = valid & (curr > 0) & (curr + ll > token_len);
                if (close) s_meta[last_t] |= (unsigned short)((seg + 1) << 1);
                seg  += (int)close;
                curr  = close ? 0 : curr;
                if (valid) s_meta[tt] |= 1;
                curr  += valid ? ll : 0;
                last_t = valid ? tt : last_t;
            }
            cur = nxt;
        }
        bool trail = (curr > 0);
        if (trail) s_meta[last_t] |= (unsigned short)((seg + 1) << 1);
        seg += (int)trail;
        g_newlen[b] = seg;
    }
    __syncthreads();

    // Cooperative writeback of metadata.
    g_meta[b * T_ + t] = s_meta[t];
}

// ---------------------------------------------------------------------------
// Kernel 2 (data plane + rank), LOAD-BALANCED: 1024 blocks x 64 threads.
// Block (b = x>>1, half = x&1) owns float4 chunks [0,63) or [63,125) of
// source column b. 1024 half-tasks over 148 SMs = 6.92 -> max 7 per SM
// (3.5 column-equivalents) vs the old 512-block grid's max 4 — removes the
// ~13% straggler tail where only 68 SMs still had work. Per-SM in-flight
// bytes unchanged (7 x 64 x 8 x 16B ~= 57KB), so latency hiding holds.
// Rank + meta are recomputed per half-block (cheap, hidden under prefetch).
// Streaming body identical to R12: read each input row once, accumulate
// valid rows, write-through rows t>=L, flush acc at segment-end flags.
// ---------------------------------------------------------------------------
__global__ __launch_bounds__(64) void merge_kernel(const float4* __restrict__ embv,
                                                   float4* __restrict__ outv,
                                                   float* __restrict__ out_len,
                                                   int write_len)
{
    __shared__ unsigned short s_meta[T_];
    __shared__ int s_warp[2];
    __shared__ int s_rank;

    int bx   = blockIdx.x;
    int b    = bx >> 1;
    int half = bx & 1;
    int i    = threadIdx.x;          // 0..63

    const long stride = (long)B_ * D4_;        // float4s per t-slab
    int  nch    = half ? (D4_ - H0) : H0;      // 62 : 63
    bool active = (i < nch);
    int  c      = half * H0 + (active ? i : 0);  // chunk index, clamped valid
    long ibase  = (long)b * D4_ + c;

    // ---- kick off prefetch pipeline first (deep MLP) ----
    float4 buf[PF];
    #pragma unroll
    for (int k = 0; k < PF; k++) buf[k] = embv[ibase + (long)k * stride];

    // ---- overlap: meta load + rank reduction while loads are in flight ----
    s_meta[i]      = g_meta[b * T_ + i];
    s_meta[i + 64] = g_meta[b * T_ + i + 64];

    int myl = g_newlen[b];
    const int4* len4 = (const int4*)g_newlen;  // 128 int4 words
    int cnt = 0;
    #pragma unroll
    for (int w = 0; w < 2; w++) {
        int wi = i + w * 64;
        int4 v4 = len4[wi];
        int j = 4 * wi;
        cnt += (v4.x > myl) || (v4.x == myl && (j + 0) < b);
        cnt += (v4.y > myl) || (v4.y == myl && (j + 1) < b);
        cnt += (v4.z > myl) || (v4.z == myl && (j + 2) < b);
        cnt += (v4.w > myl) || (v4.w == myl && (j + 3) < b);
    }
    #pragma unroll
    for (int o = 16; o > 0; o >>= 1) cnt += __shfl_down_sync(0xFFFFFFFFu, cnt, o);
    if ((i & 31) == 0) s_warp[i >> 5] = cnt;
    __syncthreads();
    if (i == 0) {
        int rank = s_warp[0] + s_warp[1];
        s_rank = rank;
        if (write_len && half == 0) out_len[rank] = (float)myl;
    }
    __syncthreads();

    int  bo    = s_rank;
    int  L     = myl;
    long obase = (long)bo * D4_ + c;

    // ---- streaming loop with 8-deep ring buffer ----
    float4 acc = make_float4(0.f, 0.f, 0.f, 0.f);

    for (int to = 0; to < T_; to += PF) {
        #pragma unroll
        for (int k = 0; k < PF; k++) {
            int t = to + k;
            float4 v = buf[k];
            if (t + PF < T_)                       // refill slot (stays PF ahead)
                buf[k] = embv[ibase + (long)(t + PF) * stride];

            unsigned int m = s_meta[t];
            if (m & 1u) {
                acc.x += v.x; acc.y += v.y; acc.z += v.z; acc.w += v.w;
            }
            if (t >= L && active)
                outv[obase + (long)t * stride] = v;

            unsigned int e = m >> 1;
            if (e && active) {
                outv[obase + (long)((int)e - 1) * stride] = acc;
                acc = make_float4(0.f, 0.f, 0.f, 0.f);
            }
        }
    }
}

// ---------------------------------------------------------------------------
extern "C" void kernel_launch(void* const* d_in, const int* in_sizes, int n_in,
                              void* d_out, int out_size)
{
    const float* emb           = (const float*)d_in[0];   // (T,B,D) fp32
    const int*   src           = (const int*)d_in[1];     // (T,B) int32
    // d_in[2] = lengths (unused by reference computation)
    const int*   token_lengths = (const int*)d_in[3];     // (VOCAB,) int32
    const int*   token_len_p   = (n_in >= 5) ? (const int*)d_in[4] : nullptr;

    float* out = (float*)d_out;
    const long emb_elems = (long)T_ * B_ * D_;
    int write_len = (out_size >= emb_elems + B_) ? 1 : 0;

    setup_kernel<<<B_, T_>>>(src, token_lengths, token_len_p);
    merge_kernel<<<2 * B_, 64>>>((const float4*)emb, (float4*)out,
                                 out + emb_elems, write_len);
}